// round 14
// baseline (speedup 1.0000x reference)
#include <cuda_runtime.h>
#include <cuda_fp16.h>
#include <mma.h>
#include <math.h>

using namespace nvcuda;

#define NMAX   50000
#define E_MAX  1600000
#define F_IN   128
#define F_HID  128
#define F_OUT  40
#define EF     16
#define EH     32
#define SCAN_B 256
#define TILE_E 512     // edges per CTA in edge kernel
#define EX_LD  24      // padded halfs per staged ex row
#define C_LD   36      // padded floats per staged c row

// ---------------- scratch (static device globals; no allocs allowed) --------
__device__ int      g_is64;
__device__ int      g_idx [2 * E_MAX];   // row[E], col[E] as int32 (clamped)
__device__ float    g_ew  [E_MAX];
__device__ float    g_deg [NMAX];
__device__ float    g_dinv[NMAX];
__device__ int      g_cnt [NMAX];
__device__ int      g_rowptr[NMAX + 1];
__device__ int      g_cursor[NMAX];
__device__ int      g_bsum[((NMAX + SCAN_B - 1) / SCAN_B) + 1];
__device__ unsigned g_srcw[E_MAX];       // (src:16 | fp16 weight:16)
__device__ __half   g_h1h [(size_t)NMAX * F_HID];
__device__ __half   g_acc1h[(size_t)NMAX * F_HID];
__device__ __half   g_h2h [(size_t)NMAX * F_OUT];

__device__ __forceinline__ float4 h4_to_f4(uint2 v) {
    __half2 h0 = *reinterpret_cast<__half2*>(&v.x);
    __half2 h1 = *reinterpret_cast<__half2*>(&v.y);
    float2 f0 = __half22float2(h0);
    float2 f1 = __half22float2(h1);
    return make_float4(f0.x, f0.y, f1.x, f1.y);
}
__device__ __forceinline__ uint2 f4_to_h4(float4 v) {
    __half2 a = __floats2half2_rn(v.x, v.y);
    __half2 b = __floats2half2_rn(v.z, v.w);
    uint2 r;
    r.x = *reinterpret_cast<unsigned int*>(&a);
    r.y = *reinterpret_cast<unsigned int*>(&b);
    return r;
}
__device__ __forceinline__ void unpack_sw(unsigned v, int& src, float& w) {
    src = (int)(v >> 16);
    unsigned short hbits = (unsigned short)(v & 0xffffu);
    w = __half2float(__ushort_as_half(hbits));
}

// ---------------- node init (cnt=0, deg=1) + dtype detect in block 0 --------
__global__ void k_node_init(const unsigned int* __restrict__ p, int n) {
    int i = blockIdx.x * blockDim.x + threadIdx.x;
    if (blockIdx.x == 0) {
        unsigned v = p[2 * threadIdx.x + 1];
        int any = __syncthreads_or(v != 0u);
        if (threadIdx.x == 0) g_is64 = any ? 0 : 1;
    }
    if (i < n) { g_cnt[i] = 0; g_deg[i] = 1.0f; }
}

// ---------------- FUSED per-edge: idx convert, histogram, tensor-core MLP ---
__global__ __launch_bounds__(256) void k_edge_all(
    const void* __restrict__ ei, const float* __restrict__ ex,
    const float* __restrict__ W1, const float* __restrict__ b1,
    const float* __restrict__ W2, const float* __restrict__ b2, int E, int n)
{
    __shared__ __half s_exh[TILE_E * EX_LD];
    __shared__ __half s_w1h[16 * 32];
    __shared__ float  s_c[8][16 * C_LD];
    __shared__ float  s_b1[EH];
    __shared__ float  s_w2[EH];
    __shared__ float  s_b2;

    int tid = threadIdx.x;
    int e_base = blockIdx.x * TILE_E;

    {
        int i0 = tid * 2;
        s_w1h[i0]     = __float2half_rn(W1[i0]);
        s_w1h[i0 + 1] = __float2half_rn(W1[i0 + 1]);
    }
    if (tid < EH) { s_b1[tid] = b1[tid]; s_w2[tid] = W2[tid]; }
    if (tid == 0) s_b2 = b2[0];

    {
        int e0 = e_base + tid * 2;
        int e1 = e0 + 1;
        if (e0 < E) {
            int r0, c0;
            if (g_is64) { const long long* p = (const long long*)ei;
                          r0 = (int)p[e0]; c0 = (int)p[E + e0]; }
            else        { const int* p = (const int*)ei;
                          r0 = p[e0]; c0 = p[E + e0]; }
            r0 = r0 < 0 ? 0 : (r0 >= n ? n - 1 : r0);
            c0 = c0 < 0 ? 0 : (c0 >= n ? n - 1 : c0);
            g_idx[e0] = r0; g_idx[E + e0] = c0;
            atomicAdd(&g_cnt[c0], 1);
            if (e1 < E) {
                int r1, c1;
                if (g_is64) { const long long* p = (const long long*)ei;
                              r1 = (int)p[e1]; c1 = (int)p[E + e1]; }
                else        { const int* p = (const int*)ei;
                              r1 = p[e1]; c1 = p[E + e1]; }
                r1 = r1 < 0 ? 0 : (r1 >= n ? n - 1 : r1);
                c1 = c1 < 0 ? 0 : (c1 >= n ? n - 1 : c1);
                g_idx[e1] = r1; g_idx[E + e1] = c1;
                atomicAdd(&g_cnt[c1], 1);
            }
        }
    }

    {
        const float4* ex4 = (const float4*)ex;
#pragma unroll
        for (int it = 0; it < 8; it++) {
            int f = tid + it * 256;
            int e_loc = f >> 2, q = f & 3;
            int e = e_base + e_loc;
            float4 v = (e < E) ? ex4[(size_t)e * 4 + q]
                               : make_float4(0.f, 0.f, 0.f, 0.f);
            __half2* dst = (__half2*)(s_exh + e_loc * EX_LD + q * 4);
            dst[0] = __floats2half2_rn(v.x, v.y);
            dst[1] = __floats2half2_rn(v.z, v.w);
        }
    }
    __syncthreads();

    int wid = tid >> 5, lane = tid & 31;
    wmma::fragment<wmma::matrix_b, 16, 16, 16, __half, wmma::row_major> bf0, bf1;
    wmma::load_matrix_sync(bf0, s_w1h,      32);
    wmma::load_matrix_sync(bf1, s_w1h + 16, 32);

    float* cbuf = s_c[wid];
    int row = lane & 15, hh = lane >> 4;
    const float* bb = s_b1 + hh * 16;
    const float* ww = s_w2 + hh * 16;

#pragma unroll
    for (int t4 = 0; t4 < 4; t4++) {
        int tile = wid * 4 + t4;
        wmma::fragment<wmma::matrix_a, 16, 16, 16, __half, wmma::row_major> af;
        wmma::load_matrix_sync(af, s_exh + tile * 16 * EX_LD, EX_LD);
        wmma::fragment<wmma::accumulator, 16, 16, 16, float> c0, c1;
        wmma::fill_fragment(c0, 0.f);
        wmma::fill_fragment(c1, 0.f);
        wmma::mma_sync(c0, af, bf0, c0);
        wmma::mma_sync(c1, af, bf1, c1);
        wmma::store_matrix_sync(cbuf,      c0, C_LD, wmma::mem_row_major);
        wmma::store_matrix_sync(cbuf + 16, c1, C_LD, wmma::mem_row_major);
        __syncwarp();

        int e = e_base + tile * 16 + row;
        const float* crow = cbuf + row * C_LD + hh * 16;
        float z = 0.f;
#pragma unroll
        for (int k = 0; k < 16; k++) {
            float a = crow[k] + bb[k];
            z = fmaf(fmaxf(a, 0.f), ww[k], z);
        }
        z += __shfl_xor_sync(0xffffffffu, z, 16);
        if (hh == 0 && e < E) {
            float w = 1.0f / (1.0f + __expf(-(z + s_b2)));
            g_ew[e] = w;
            atomicAdd(&g_deg[g_idx[E + e]], w);
        }
        __syncwarp();
    }
}

// ---------------- scan pass 1 ----------------------------------------------
__global__ __launch_bounds__(SCAN_B) void k_scan1(int n) {
    __shared__ int warp_sums[8];
    int tid = threadIdx.x, lane = tid & 31, wid = tid >> 5;
    int i = blockIdx.x * SCAN_B + tid;
    int v = (i < n) ? g_cnt[i] : 0;
    int incl = v;
#pragma unroll
    for (int o = 1; o < 32; o <<= 1) {
        int t = __shfl_up_sync(0xffffffffu, incl, o);
        if (lane >= o) incl += t;
    }
    if (lane == 31) warp_sums[wid] = incl;
    __syncthreads();
    if (wid == 0 && lane < 8) {
        int ws = warp_sums[lane];
#pragma unroll
        for (int o = 1; o < 8; o <<= 1) {
            int t = __shfl_up_sync(0xffu, ws, o);
            if (lane >= o) ws += t;
        }
        warp_sums[lane] = ws;
    }
    __syncthreads();
    int excl = incl - v + (wid > 0 ? warp_sums[wid - 1] : 0);
    if (i < n) g_rowptr[i] = excl;
    if (tid == SCAN_B - 1) g_bsum[blockIdx.x] = excl + v;
}

// ---------------- scan pass 2 ----------------------------------------------
__global__ __launch_bounds__(SCAN_B) void k_scan2(int nblk) {
    __shared__ int s[SCAN_B];
    int tid = threadIdx.x;
    s[tid] = (tid < nblk) ? g_bsum[tid] : 0;
    __syncthreads();
    for (int o = 1; o < SCAN_B; o <<= 1) {
        int t = (tid >= o) ? s[tid - o] : 0;
        __syncthreads();
        s[tid] += t;
        __syncthreads();
    }
    if (tid < nblk) g_bsum[tid] = (tid > 0) ? s[tid - 1] : 0;
}

// ---------------- scan pass 3: offsets + cursor + dinv ----------------------
__global__ __launch_bounds__(SCAN_B) void k_scan3(int n, int E) {
    int i = blockIdx.x * SCAN_B + threadIdx.x;
    if (i < n) {
        int v = g_rowptr[i] + g_bsum[blockIdx.x];
        g_rowptr[i] = v;
        g_cursor[i] = v;
        float d = g_deg[i];
        g_dinv[i] = (d > 0.0f) ? rsqrtf(d) : 0.0f;
    }
    if (i == 0) g_rowptr[n] = E;
}

// ---------------- build CSR: scatter packed (src|w) into slot of dst --------
__global__ void k_permute(int E) {
    int e = blockIdx.x * blockDim.x + threadIdx.x;
    if (e >= E) return;
    int r = g_idx[e], c = g_idx[E + e];
    float w = g_ew[e] * g_dinv[r] * g_dinv[c];
    int pos = atomicAdd(&g_cursor[c], 1);
    unsigned hw = (unsigned)__half_as_ushort(__float2half_rn(w));
    g_srcw[pos] = ((unsigned)r << 16) | hw;
}

// ---------------- h1 = x @ Wg1  -> fp16 --------------------------------------
#define G1_ROWS 32
__global__ __launch_bounds__(128) void k_gemm1(
    const float* __restrict__ x, const float* __restrict__ W, int n)
{
    __shared__ float4 xs[G1_ROWS * 32];
    int r0  = blockIdx.x * G1_ROWS;
    int tid = threadIdx.x;
    for (int i = tid; i < G1_ROWS * 32; i += 128) {
        int rr = i >> 5, kk = i & 31;
        int row = r0 + rr;
        xs[i] = (row < n) ? ((const float4*)x)[(size_t)row * 32 + kk]
                          : make_float4(0.f, 0.f, 0.f, 0.f);
    }
    __syncthreads();

    int j = tid;
    float acc[G1_ROWS];
#pragma unroll
    for (int r = 0; r < G1_ROWS; r++) acc[r] = 0.0f;

    for (int k4 = 0; k4 < 32; k4++) {
        float w0 = W[(k4*4+0) * F_HID + j];
        float w1 = W[(k4*4+1) * F_HID + j];
        float w2 = W[(k4*4+2) * F_HID + j];
        float w3 = W[(k4*4+3) * F_HID + j];
#pragma unroll
        for (int r = 0; r < G1_ROWS; r++) {
            float4 xv = xs[r * 32 + k4];
            acc[r] = fmaf(xv.x, w0, fmaf(xv.y, w1, fmaf(xv.z, w2, fmaf(xv.w, w3, acc[r]))));
        }
    }
#pragma unroll
    for (int r = 0; r < G1_ROWS; r++) {
        int row = r0 + r;
        if (row < n) g_h1h[(size_t)row * F_HID + j] = __float2half_rn(acc[r]);
    }
}

// ---------------- conv1 gather: lane-parallel srcw batch + shfl distribute --
__global__ __launch_bounds__(256) void k_gather1(const float* __restrict__ bg1, int n)
{
    int c    = (blockIdx.x * blockDim.x + threadIdx.x) >> 5;
    int lane = threadIdx.x & 31;
    if (c >= n) return;
    float di = g_dinv[c];
    float sl = di * di;

    float4 acc = ((const float4*)bg1)[lane];
    {
        const uint2* rp = (const uint2*)(g_h1h + (size_t)c * F_HID);
        float4 hv = h4_to_f4(rp[lane]);
        acc.x = fmaf(sl, hv.x, acc.x);
        acc.y = fmaf(sl, hv.y, acc.y);
        acc.z = fmaf(sl, hv.z, acc.z);
        acc.w = fmaf(sl, hv.w, acc.w);
    }

    int beg = g_rowptr[c], end = g_rowptr[c + 1];
    float4 a2 = make_float4(0.f, 0.f, 0.f, 0.f);

    for (int base = beg; base < end; base += 32) {
        // all lanes fetch one srcw word (coalesced); distribute via shfl
        int m = end - base; if (m > 32) m = 32;
        unsigned my = (base + lane < end) ? g_srcw[base + lane] : 0u;
        int jj = 0;
        for (; jj + 1 < m; jj += 2) {
            unsigned v0 = __shfl_sync(0xffffffffu, my, jj);
            unsigned v1 = __shfl_sync(0xffffffffu, my, jj + 1);
            int s0, s1; float w0, w1;
            unpack_sw(v0, s0, w0);
            unpack_sw(v1, s1, w1);
            float4 h0 = h4_to_f4(((const uint2*)(g_h1h + (size_t)s0 * F_HID))[lane]);
            float4 h1 = h4_to_f4(((const uint2*)(g_h1h + (size_t)s1 * F_HID))[lane]);
            acc.x = fmaf(w0, h0.x, acc.x);  a2.x = fmaf(w1, h1.x, a2.x);
            acc.y = fmaf(w0, h0.y, acc.y);  a2.y = fmaf(w1, h1.y, a2.y);
            acc.z = fmaf(w0, h0.z, acc.z);  a2.z = fmaf(w1, h1.z, a2.z);
            acc.w = fmaf(w0, h0.w, acc.w);  a2.w = fmaf(w1, h1.w, a2.w);
        }
        if (jj < m) {
            unsigned v0 = __shfl_sync(0xffffffffu, my, jj);
            int s0; float w0;
            unpack_sw(v0, s0, w0);
            float4 h0 = h4_to_f4(((const uint2*)(g_h1h + (size_t)s0 * F_HID))[lane]);
            acc.x = fmaf(w0, h0.x, acc.x);
            acc.y = fmaf(w0, h0.y, acc.y);
            acc.z = fmaf(w0, h0.z, acc.z);
            acc.w = fmaf(w0, h0.w, acc.w);
        }
    }
    acc.x = fmaxf(acc.x + a2.x, 0.f);
    acc.y = fmaxf(acc.y + a2.y, 0.f);
    acc.z = fmaxf(acc.z + a2.z, 0.f);
    acc.w = fmaxf(acc.w + a2.w, 0.f);
    ((uint2*)(g_acc1h + (size_t)c * F_HID))[lane] = f4_to_h4(acc);
}

// ---------------- h2 = acc1 @ Wg2 (acc1 fp16, already ReLU'd) -> fp16 -------
__global__ __launch_bounds__(128) void k_gemm2(const float* __restrict__ W, int n)
{
    __shared__ float sw[F_HID * F_OUT];
    int tid = threadIdx.x;
    for (int i = tid; i < F_HID * F_OUT; i += 128) sw[i] = W[i];
    __syncthreads();

    int warp = tid >> 5, lane = tid & 31;
    int rbase = blockIdx.x * 16 + warp * 4;
    float accA[4] = {0.f, 0.f, 0.f, 0.f};
    float accB[4] = {0.f, 0.f, 0.f, 0.f};
    bool hiLane = (lane < 8);

    for (int k4 = 0; k4 < 32; k4++) {
        float w0[4], w1[4];
#pragma unroll
        for (int i = 0; i < 4; i++) {
            int k = k4 * 4 + i;
            w0[i] = sw[k * F_OUT + lane];
            w1[i] = hiLane ? sw[k * F_OUT + 32 + lane] : 0.0f;
        }
#pragma unroll
        for (int r = 0; r < 4; r++) {
            int rowi = rbase + r;
            if (rowi < n) {
                const uint2* xp = (const uint2*)(g_acc1h + (size_t)rowi * F_HID);
                float4 xv = h4_to_f4(xp[k4]);
                accA[r] = fmaf(xv.x, w0[0], fmaf(xv.y, w0[1], fmaf(xv.z, w0[2], fmaf(xv.w, w0[3], accA[r]))));
                accB[r] = fmaf(xv.x, w1[0], fmaf(xv.y, w1[1], fmaf(xv.z, w1[2], fmaf(xv.w, w1[3], accB[r]))));
            }
        }
    }
#pragma unroll
    for (int r = 0; r < 4; r++) {
        int rowi = rbase + r;
        if (rowi < n) {
            g_h2h[(size_t)rowi * F_OUT + lane] = __float2half_rn(accA[r]);
            if (hiLane) g_h2h[(size_t)rowi * F_OUT + 32 + lane] = __float2half_rn(accB[r]);
        }
    }
}

// ---------------- conv2 gather: lane-parallel srcw batch + shfl distribute --
__global__ __launch_bounds__(256) void k_gather2(float* __restrict__ out,
                                                 const float* __restrict__ bg2, int n)
{
    int c    = (blockIdx.x * blockDim.x + threadIdx.x) >> 5;
    int lane = threadIdx.x & 31;
    if (c >= n) return;
    bool act = (lane < 20);
    float di = g_dinv[c];
    float sl = di * di;

    float2 acc = make_float2(0.f, 0.f);
    if (act) {
        acc = ((const float2*)bg2)[lane];
        const __half2* rp = (const __half2*)(g_h2h + (size_t)c * F_OUT);
        float2 hv = __half22float2(rp[lane]);
        acc.x = fmaf(sl, hv.x, acc.x);
        acc.y = fmaf(sl, hv.y, acc.y);
    }
    float2 a2 = make_float2(0.f, 0.f);

    int beg = g_rowptr[c], end = g_rowptr[c + 1];
    for (int base = beg; base < end; base += 32) {
        int m = end - base; if (m > 32) m = 32;
        unsigned my = (base + lane < end) ? g_srcw[base + lane] : 0u;
        int jj = 0;
        for (; jj + 1 < m; jj += 2) {
            unsigned v0 = __shfl_sync(0xffffffffu, my, jj);
            unsigned v1 = __shfl_sync(0xffffffffu, my, jj + 1);
            if (act) {
                int s0, s1; float w0, w1;
                unpack_sw(v0, s0, w0);
                unpack_sw(v1, s1, w1);
                float2 h0 = __half22float2(((const __half2*)(g_h2h + (size_t)s0 * F_OUT))[lane]);
                float2 h1 = __half22float2(((const __half2*)(g_h2h + (size_t)s1 * F_OUT))[lane]);
                acc.x = fmaf(w0, h0.x, acc.x);  a2.x = fmaf(w1, h1.x, a2.x);
                acc.y = fmaf(w0, h0.y, acc.y);  a2.y = fmaf(w1, h1.y, a2.y);
            }
        }
        if (jj < m) {
            unsigned v0 = __shfl_sync(0xffffffffu, my, jj);
            if (act) {
                int s0; float w0;
                unpack_sw(v0, s0, w0);
                float2 h0 = __half22float2(((const __half2*)(g_h2h + (size_t)s0 * F_OUT))[lane]);
                acc.x = fmaf(w0, h0.x, acc.x);
                acc.y = fmaf(w0, h0.y, acc.y);
            }
        }
    }
    if (act) {
        acc.x += a2.x;
        acc.y += a2.y;
        ((float2*)(out + (size_t)c * F_OUT))[lane] = acc;
    }
}

// ---------------- launch -----------------------------------------------------
extern "C" void kernel_launch(void* const* d_in, const int* in_sizes, int n_in,
                              void* d_out, int out_size)
{
    const float* x   = (const float*)d_in[0];
    const void*  ei  = d_in[1];
    const float* ex  = (const float*)d_in[2];
    const float* W1  = (const float*)d_in[3];
    const float* b1  = (const float*)d_in[4];
    const float* W2  = (const float*)d_in[5];
    const float* b2  = (const float*)d_in[6];
    const float* Wg1 = (const float*)d_in[7];
    const float* bg1 = (const float*)d_in[8];
    const float* Wg2 = (const float*)d_in[9];
    const float* bg2 = (const float*)d_in[10];
    float* out = (float*)d_out;

    int n = in_sizes[0] / F_IN;       // 50000
    int E = in_sizes[2] / EF;         // 1600000
    int nblk = (n + SCAN_B - 1) / SCAN_B;

    static cudaStream_t s2 = nullptr;
    static cudaEvent_t  evFork = nullptr, evJoin = nullptr;
    if (s2 == nullptr) {
        cudaStreamCreateWithFlags(&s2, cudaStreamNonBlocking);
        cudaEventCreateWithFlags(&evFork, cudaEventDisableTiming);
        cudaEventCreateWithFlags(&evJoin, cudaEventDisableTiming);
    }

    // fork: gemm1 depends only on x,Wg1 — run on side stream
    cudaEventRecord(evFork, 0);
    cudaStreamWaitEvent(s2, evFork, 0);
    k_gemm1<<<(n + G1_ROWS - 1) / G1_ROWS, 128, 0, s2>>>(x, Wg1, n);
    cudaEventRecord(evJoin, s2);

    // main stream: fused edge pipeline
    k_node_init<<<(n + 255) / 256, 256>>>((const unsigned int*)ei, n);

    int eblk = (E + TILE_E - 1) / TILE_E;
    k_edge_all<<<eblk, 256>>>(ei, ex, W1, b1, W2, b2, E, n);

    k_scan1<<<nblk, SCAN_B>>>(n);
    k_scan2<<<1, SCAN_B>>>(nblk);
    k_scan3<<<nblk, SCAN_B>>>(n, E);

    k_permute<<<(E + 255) / 256, 256>>>(E);

    // join: gather1 needs both gemm1 (h1) and permute (CSR)
    cudaStreamWaitEvent(0, evJoin, 0);
    k_gather1<<<(n * 32 + 255) / 256, 256>>>(bg1, n);

    k_gemm2<<<(n + 15) / 16, 128>>>(Wg2, n);

    k_gather2<<<(n * 32 + 255) / 256, 256>>>(out, bg2, n);
}

// round 16
// speedup vs baseline: 1.1707x; 1.1707x over previous
#include <cuda_runtime.h>
#include <cuda_fp16.h>
#include <mma.h>
#include <math.h>

using namespace nvcuda;

#define NMAX   50000
#define E_MAX  1600000
#define F_IN   128
#define F_HID  128
#define F_OUT  40
#define EF     16
#define EH     32
#define SCAN_B 256
#define TILE_E 512     // edges per CTA in edge kernel
#define EX_LD  24      // padded halfs per staged ex row
#define C_LD   36      // padded floats per staged c row
#define GW     16      // nodes (warps) per gather1 CTA
#define A_LD   136     // halfs per staged acc row (272B, 16B-multiple)
#define N_PAD  48      // Wg2 n padded to 48

// ---------------- scratch (static device globals; no allocs allowed) --------
__device__ int      g_is64;
__device__ int      g_idx [2 * E_MAX];   // row[E], col[E] as int32 (clamped)
__device__ float    g_ew  [E_MAX];
__device__ float    g_deg [NMAX];
__device__ float    g_dinv[NMAX];
__device__ int      g_cnt [NMAX];
__device__ int      g_rowptr[NMAX + 1];
__device__ int      g_cursor[NMAX];
__device__ int      g_bsum[((NMAX + SCAN_B - 1) / SCAN_B) + 1];
__device__ unsigned g_srcw[E_MAX];       // (src:16 | fp16 weight:16)
__device__ __half   g_h1h [(size_t)NMAX * F_HID];
__device__ __half   g_h2h [(size_t)NMAX * F_OUT];
__device__ __half   g_wg2h[F_HID * N_PAD];   // Wg2 fp16, n padded to 48 (zeros)

__device__ __forceinline__ float4 h4_to_f4(uint2 v) {
    __half2 h0 = *reinterpret_cast<__half2*>(&v.x);
    __half2 h1 = *reinterpret_cast<__half2*>(&v.y);
    float2 f0 = __half22float2(h0);
    float2 f1 = __half22float2(h1);
    return make_float4(f0.x, f0.y, f1.x, f1.y);
}
__device__ __forceinline__ uint2 f4_to_h4(float4 v) {
    __half2 a = __floats2half2_rn(v.x, v.y);
    __half2 b = __floats2half2_rn(v.z, v.w);
    uint2 r;
    r.x = *reinterpret_cast<unsigned int*>(&a);
    r.y = *reinterpret_cast<unsigned int*>(&b);
    return r;
}
__device__ __forceinline__ void unpack_sw(unsigned v, int& src, float& w) {
    src = (int)(v >> 16);
    unsigned short hbits = (unsigned short)(v & 0xffffu);
    w = __half2float(__ushort_as_half(hbits));
}

// ---------------- node init: cnt=0, deg=1; detect dtype; convert Wg2->fp16 --
__global__ void k_node_init(const unsigned int* __restrict__ p,
                            const float* __restrict__ Wg2, int n) {
    int i = blockIdx.x * blockDim.x + threadIdx.x;
    if (blockIdx.x == 0) {
        unsigned v = p[2 * threadIdx.x + 1];
        int any = __syncthreads_or(v != 0u);
        if (threadIdx.x == 0) g_is64 = any ? 0 : 1;
    }
    if (i < F_HID * N_PAD) {
        int k = i / N_PAD, nn = i % N_PAD;
        g_wg2h[i] = (nn < F_OUT) ? __float2half_rn(Wg2[k * F_OUT + nn])
                                 : __ushort_as_half((unsigned short)0);
    }
    if (i < n) { g_cnt[i] = 0; g_deg[i] = 1.0f; }
}

// ---------------- FUSED per-edge: idx convert, histogram, tensor-core MLP ---
__global__ __launch_bounds__(256) void k_edge_all(
    const void* __restrict__ ei, const float* __restrict__ ex,
    const float* __restrict__ W1, const float* __restrict__ b1,
    const float* __restrict__ W2, const float* __restrict__ b2, int E, int n)
{
    __shared__ __half s_exh[TILE_E * EX_LD];
    __shared__ __half s_w1h[16 * 32];
    __shared__ float  s_c[8][16 * C_LD];
    __shared__ float  s_b1[EH];
    __shared__ float  s_w2[EH];
    __shared__ float  s_b2;

    int tid = threadIdx.x;
    int e_base = blockIdx.x * TILE_E;

    {
        int i0 = tid * 2;
        s_w1h[i0]     = __float2half_rn(W1[i0]);
        s_w1h[i0 + 1] = __float2half_rn(W1[i0 + 1]);
    }
    if (tid < EH) { s_b1[tid] = b1[tid]; s_w2[tid] = W2[tid]; }
    if (tid == 0) s_b2 = b2[0];

    {
        int e0 = e_base + tid * 2;
        int e1 = e0 + 1;
        if (e0 < E) {
            int r0, c0;
            if (g_is64) { const long long* p = (const long long*)ei;
                          r0 = (int)p[e0]; c0 = (int)p[E + e0]; }
            else        { const int* p = (const int*)ei;
                          r0 = p[e0]; c0 = p[E + e0]; }
            r0 = r0 < 0 ? 0 : (r0 >= n ? n - 1 : r0);
            c0 = c0 < 0 ? 0 : (c0 >= n ? n - 1 : c0);
            g_idx[e0] = r0; g_idx[E + e0] = c0;
            atomicAdd(&g_cnt[c0], 1);
            if (e1 < E) {
                int r1, c1;
                if (g_is64) { const long long* p = (const long long*)ei;
                              r1 = (int)p[e1]; c1 = (int)p[E + e1]; }
                else        { const int* p = (const int*)ei;
                              r1 = p[e1]; c1 = p[E + e1]; }
                r1 = r1 < 0 ? 0 : (r1 >= n ? n - 1 : r1);
                c1 = c1 < 0 ? 0 : (c1 >= n ? n - 1 : c1);
                g_idx[e1] = r1; g_idx[E + e1] = c1;
                atomicAdd(&g_cnt[c1], 1);
            }
        }
    }

    {
        const float4* ex4 = (const float4*)ex;
#pragma unroll
        for (int it = 0; it < 8; it++) {
            int f = tid + it * 256;
            int e_loc = f >> 2, q = f & 3;
            int e = e_base + e_loc;
            float4 v = (e < E) ? ex4[(size_t)e * 4 + q]
                               : make_float4(0.f, 0.f, 0.f, 0.f);
            __half2* dst = (__half2*)(s_exh + e_loc * EX_LD + q * 4);
            dst[0] = __floats2half2_rn(v.x, v.y);
            dst[1] = __floats2half2_rn(v.z, v.w);
        }
    }
    __syncthreads();

    int wid = tid >> 5, lane = tid & 31;
    wmma::fragment<wmma::matrix_b, 16, 16, 16, __half, wmma::row_major> bf0, bf1;
    wmma::load_matrix_sync(bf0, s_w1h,      32);
    wmma::load_matrix_sync(bf1, s_w1h + 16, 32);

    float* cbuf = s_c[wid];
    int row = lane & 15, hh = lane >> 4;
    const float* bb = s_b1 + hh * 16;
    const float* ww = s_w2 + hh * 16;

#pragma unroll
    for (int t4 = 0; t4 < 4; t4++) {
        int tile = wid * 4 + t4;
        wmma::fragment<wmma::matrix_a, 16, 16, 16, __half, wmma::row_major> af;
        wmma::load_matrix_sync(af, s_exh + tile * 16 * EX_LD, EX_LD);
        wmma::fragment<wmma::accumulator, 16, 16, 16, float> c0, c1;
        wmma::fill_fragment(c0, 0.f);
        wmma::fill_fragment(c1, 0.f);
        wmma::mma_sync(c0, af, bf0, c0);
        wmma::mma_sync(c1, af, bf1, c1);
        wmma::store_matrix_sync(cbuf,      c0, C_LD, wmma::mem_row_major);
        wmma::store_matrix_sync(cbuf + 16, c1, C_LD, wmma::mem_row_major);
        __syncwarp();

        int e = e_base + tile * 16 + row;
        const float* crow = cbuf + row * C_LD + hh * 16;
        float z = 0.f;
#pragma unroll
        for (int k = 0; k < 16; k++) {
            float a = crow[k] + bb[k];
            z = fmaf(fmaxf(a, 0.f), ww[k], z);
        }
        z += __shfl_xor_sync(0xffffffffu, z, 16);
        if (hh == 0 && e < E) {
            float w = 1.0f / (1.0f + __expf(-(z + s_b2)));
            g_ew[e] = w;
            atomicAdd(&g_deg[g_idx[E + e]], w);
        }
        __syncwarp();
    }
}

// ---------------- scan pass 1 ----------------------------------------------
__global__ __launch_bounds__(SCAN_B) void k_scan1(int n) {
    __shared__ int warp_sums[8];
    int tid = threadIdx.x, lane = tid & 31, wid = tid >> 5;
    int i = blockIdx.x * SCAN_B + tid;
    int v = (i < n) ? g_cnt[i] : 0;
    int incl = v;
#pragma unroll
    for (int o = 1; o < 32; o <<= 1) {
        int t = __shfl_up_sync(0xffffffffu, incl, o);
        if (lane >= o) incl += t;
    }
    if (lane == 31) warp_sums[wid] = incl;
    __syncthreads();
    if (wid == 0 && lane < 8) {
        int ws = warp_sums[lane];
#pragma unroll
        for (int o = 1; o < 8; o <<= 1) {
            int t = __shfl_up_sync(0xffu, ws, o);
            if (lane >= o) ws += t;
        }
        warp_sums[lane] = ws;
    }
    __syncthreads();
    int excl = incl - v + (wid > 0 ? warp_sums[wid - 1] : 0);
    if (i < n) g_rowptr[i] = excl;
    if (tid == SCAN_B - 1) g_bsum[blockIdx.x] = excl + v;
}

// ---------------- scan pass 2 ----------------------------------------------
__global__ __launch_bounds__(SCAN_B) void k_scan2(int nblk) {
    __shared__ int s[SCAN_B];
    int tid = threadIdx.x;
    s[tid] = (tid < nblk) ? g_bsum[tid] : 0;
    __syncthreads();
    for (int o = 1; o < SCAN_B; o <<= 1) {
        int t = (tid >= o) ? s[tid - o] : 0;
        __syncthreads();
        s[tid] += t;
        __syncthreads();
    }
    if (tid < nblk) g_bsum[tid] = (tid > 0) ? s[tid - 1] : 0;
}

// ---------------- scan pass 3: offsets + cursor + dinv ----------------------
__global__ __launch_bounds__(SCAN_B) void k_scan3(int n, int E) {
    int i = blockIdx.x * SCAN_B + threadIdx.x;
    if (i < n) {
        int v = g_rowptr[i] + g_bsum[blockIdx.x];
        g_rowptr[i] = v;
        g_cursor[i] = v;
        float d = g_deg[i];
        g_dinv[i] = (d > 0.0f) ? rsqrtf(d) : 0.0f;
    }
    if (i == 0) g_rowptr[n] = E;
}

// ---------------- build CSR: scatter packed (src|w) into slot of dst --------
__global__ void k_permute(int E) {
    int e = blockIdx.x * blockDim.x + threadIdx.x;
    if (e >= E) return;
    int r = g_idx[e], c = g_idx[E + e];
    float w = g_ew[e] * g_dinv[r] * g_dinv[c];
    int pos = atomicAdd(&g_cursor[c], 1);
    unsigned hw = (unsigned)__half_as_ushort(__float2half_rn(w));
    g_srcw[pos] = ((unsigned)r << 16) | hw;
}

// ---------------- h1 = x @ Wg1  -> fp16 --------------------------------------
#define G1_ROWS 32
__global__ __launch_bounds__(128) void k_gemm1(
    const float* __restrict__ x, const float* __restrict__ W, int n)
{
    __shared__ float4 xs[G1_ROWS * 32];
    int r0  = blockIdx.x * G1_ROWS;
    int tid = threadIdx.x;
    for (int i = tid; i < G1_ROWS * 32; i += 128) {
        int rr = i >> 5, kk = i & 31;
        int row = r0 + rr;
        xs[i] = (row < n) ? ((const float4*)x)[(size_t)row * 32 + kk]
                          : make_float4(0.f, 0.f, 0.f, 0.f);
    }
    __syncthreads();

    int j = tid;
    float acc[G1_ROWS];
#pragma unroll
    for (int r = 0; r < G1_ROWS; r++) acc[r] = 0.0f;

    for (int k4 = 0; k4 < 32; k4++) {
        float w0 = W[(k4*4+0) * F_HID + j];
        float w1 = W[(k4*4+1) * F_HID + j];
        float w2 = W[(k4*4+2) * F_HID + j];
        float w3 = W[(k4*4+3) * F_HID + j];
#pragma unroll
        for (int r = 0; r < G1_ROWS; r++) {
            float4 xv = xs[r * 32 + k4];
            acc[r] = fmaf(xv.x, w0, fmaf(xv.y, w1, fmaf(xv.z, w2, fmaf(xv.w, w3, acc[r]))));
        }
    }
#pragma unroll
    for (int r = 0; r < G1_ROWS; r++) {
        int row = r0 + r;
        if (row < n) g_h1h[(size_t)row * F_HID + j] = __float2half_rn(acc[r]);
    }
}

// ---------------- conv1 gather FUSED with gemm2 -----------------------------
// 16 warps = 16 nodes per CTA. Each warp gathers its node (R13 inner loop),
// stages relu'd fp16 row in smem; warps 0-2 then do h2 = A[16,128]@Wg2[128,48]
// via wmma and the CTA writes h2 cols 0..39 to global (strided, all 640 elems).
__global__ __launch_bounds__(512) void k_gather1(const float* __restrict__ bg1, int n)
{
    __shared__ __align__(32) __half s_a[GW * A_LD];        // 16 x 136 halfs
    __shared__ __align__(32) __half s_w[F_HID * N_PAD];    // 128 x 48 halfs, 12KB
    __shared__ __align__(32) float  s_d[16 * N_PAD];       // 16 x 48 fp32, 3KB

    int tid = threadIdx.x, wid = tid >> 5, lane = tid & 31;

    // stage Wg2h (coalesced 4B copies: 3072 words / 512 threads = 6 each)
    {
        const unsigned* src = (const unsigned*)g_wg2h;
        unsigned* dst = (unsigned*)s_w;
#pragma unroll
        for (int i = 0; i < (F_HID * N_PAD / 2) / 512; i++)
            dst[tid + i * 512] = src[tid + i * 512];
    }

    int c = blockIdx.x * GW + wid;
    float4 acc = make_float4(0.f, 0.f, 0.f, 0.f);
    if (c < n) {
        float di = g_dinv[c];
        float sl = di * di;
        acc = ((const float4*)bg1)[lane];
        {
            const uint2* rp = (const uint2*)(g_h1h + (size_t)c * F_HID);
            float4 hv = h4_to_f4(rp[lane]);
            acc.x = fmaf(sl, hv.x, acc.x);
            acc.y = fmaf(sl, hv.y, acc.y);
            acc.z = fmaf(sl, hv.z, acc.z);
            acc.w = fmaf(sl, hv.w, acc.w);
        }
        int beg = g_rowptr[c], end = g_rowptr[c + 1];
        float4 a2 = make_float4(0.f, 0.f, 0.f, 0.f);
        int j = beg;
        for (; j + 1 < end; j += 2) {
            unsigned m0 = g_srcw[j];
            unsigned m1 = g_srcw[j + 1];
            int s0, s1; float w0, w1;
            unpack_sw(m0, s0, w0);
            unpack_sw(m1, s1, w1);
            float4 v0 = h4_to_f4(((const uint2*)(g_h1h + (size_t)s0 * F_HID))[lane]);
            float4 v1 = h4_to_f4(((const uint2*)(g_h1h + (size_t)s1 * F_HID))[lane]);
            acc.x = fmaf(w0, v0.x, acc.x);  a2.x = fmaf(w1, v1.x, a2.x);
            acc.y = fmaf(w0, v0.y, acc.y);  a2.y = fmaf(w1, v1.y, a2.y);
            acc.z = fmaf(w0, v0.z, acc.z);  a2.z = fmaf(w1, v1.z, a2.z);
            acc.w = fmaf(w0, v0.w, acc.w);  a2.w = fmaf(w1, v1.w, a2.w);
        }
        if (j < end) {
            int s0; float w0;
            unpack_sw(g_srcw[j], s0, w0);
            float4 v0 = h4_to_f4(((const uint2*)(g_h1h + (size_t)s0 * F_HID))[lane]);
            acc.x = fmaf(w0, v0.x, acc.x);
            acc.y = fmaf(w0, v0.y, acc.y);
            acc.z = fmaf(w0, v0.z, acc.z);
            acc.w = fmaf(w0, v0.w, acc.w);
        }
        acc.x = fmaxf(acc.x + a2.x, 0.f);
        acc.y = fmaxf(acc.y + a2.y, 0.f);
        acc.z = fmaxf(acc.z + a2.z, 0.f);
        acc.w = fmaxf(acc.w + a2.w, 0.f);
    }
    // stage relu'd row as fp16 (zeros for out-of-range nodes)
    ((uint2*)(s_a + wid * A_LD))[lane] = f4_to_h4(acc);
    __syncthreads();

    // warps 0-2: one 16-wide n-tile each of D = A @ Wg2h
    if (wid < 3) {
        wmma::fragment<wmma::accumulator, 16, 16, 16, float> cf;
        wmma::fill_fragment(cf, 0.f);
#pragma unroll
        for (int k = 0; k < 8; k++) {
            wmma::fragment<wmma::matrix_a, 16, 16, 16, __half, wmma::row_major> af;
            wmma::fragment<wmma::matrix_b, 16, 16, 16, __half, wmma::row_major> bf;
            wmma::load_matrix_sync(af, s_a + k * 16, A_LD);
            wmma::load_matrix_sync(bf, s_w + k * 16 * N_PAD + wid * 16, N_PAD);
            wmma::mma_sync(cf, af, bf, cf);
        }
        wmma::store_matrix_sync(s_d + wid * 16, cf, N_PAD, wmma::mem_row_major);
    }
    __syncthreads();

    // write h2 cols 0..39 (16 rows x 40 = 640 halfs; strided over 512 threads)
    for (int i = tid; i < GW * F_OUT; i += 512) {
        int r = i / F_OUT, col = i % F_OUT;
        int node = blockIdx.x * GW + r;
        if (node < n)
            g_h2h[(size_t)node * F_OUT + col] = __float2half_rn(s_d[r * N_PAD + col]);
    }
}

// ---------------- conv2 gather: out = bg2 + dinv^2*h2 + sum w*h2[src] -------
__global__ __launch_bounds__(256) void k_gather2(float* __restrict__ out,
                                                 const float* __restrict__ bg2, int n)
{
    int c    = (blockIdx.x * blockDim.x + threadIdx.x) >> 5;
    int lane = threadIdx.x & 31;
    if (c >= n || lane >= 20) return;
    float di = g_dinv[c];
    float sl = di * di;

    float2 acc = ((const float2*)bg2)[lane];
    {
        const __half2* rp = (const __half2*)(g_h2h + (size_t)c * F_OUT);
        float2 hv = __half22float2(rp[lane]);
        acc.x = fmaf(sl, hv.x, acc.x);
        acc.y = fmaf(sl, hv.y, acc.y);
    }
    float2 a2 = make_float2(0.f, 0.f);

    int beg = g_rowptr[c], end = g_rowptr[c + 1];
    int j = beg;
    for (; j + 1 < end; j += 2) {
        int s0, s1; float w0, w1;
        unpack_sw(g_srcw[j], s0, w0);
        unpack_sw(g_srcw[j + 1], s1, w1);
        const __half2* p0 = (const __half2*)(g_h2h + (size_t)s0 * F_OUT);
        const __half2* p1 = (const __half2*)(g_h2h + (size_t)s1 * F_OUT);
        float2 v0 = __half22float2(p0[lane]);
        float2 v1 = __half22float2(p1[lane]);
        acc.x = fmaf(w0, v0.x, acc.x);  a2.x = fmaf(w1, v1.x, a2.x);
        acc.y = fmaf(w0, v0.y, acc.y);  a2.y = fmaf(w1, v1.y, a2.y);
    }
    if (j < end) {
        int s0; float w0;
        unpack_sw(g_srcw[j], s0, w0);
        const __half2* p0 = (const __half2*)(g_h2h + (size_t)s0 * F_OUT);
        float2 v0 = __half22float2(p0[lane]);
        acc.x = fmaf(w0, v0.x, acc.x);
        acc.y = fmaf(w0, v0.y, acc.y);
    }
    acc.x += a2.x;
    acc.y += a2.y;
    ((float2*)(out + (size_t)c * F_OUT))[lane] = acc;
}

// ---------------- launch -----------------------------------------------------
extern "C" void kernel_launch(void* const* d_in, const int* in_sizes, int n_in,
                              void* d_out, int out_size)
{
    const float* x   = (const float*)d_in[0];
    const void*  ei  = d_in[1];
    const float* ex  = (const float*)d_in[2];
    const float* W1  = (const float*)d_in[3];
    const float* b1  = (const float*)d_in[4];
    const float* W2  = (const float*)d_in[5];
    const float* b2  = (const float*)d_in[6];
    const float* Wg1 = (const float*)d_in[7];
    const float* bg1 = (const float*)d_in[8];
    const float* Wg2 = (const float*)d_in[9];
    const float* bg2 = (const float*)d_in[10];
    float* out = (float*)d_out;

    int n = in_sizes[0] / F_IN;       // 50000
    int E = in_sizes[2] / EF;         // 1600000
    int nblk = (n + SCAN_B - 1) / SCAN_B;

    static cudaStream_t s2 = nullptr;
    static cudaEvent_t  evFork = nullptr, evJoin = nullptr;
    if (s2 == nullptr) {
        cudaStreamCreateWithFlags(&s2, cudaStreamNonBlocking);
        cudaEventCreateWithFlags(&evFork, cudaEventDisableTiming);
        cudaEventCreateWithFlags(&evJoin, cudaEventDisableTiming);
    }

    // fork: gemm1 depends only on x,Wg1 — run on side stream
    cudaEventRecord(evFork, 0);
    cudaStreamWaitEvent(s2, evFork, 0);
    k_gemm1<<<(n + G1_ROWS - 1) / G1_ROWS, 128, 0, s2>>>(x, Wg1, n);
    cudaEventRecord(evJoin, s2);

    // main stream: fused edge pipeline
    k_node_init<<<(n + 255) / 256, 256>>>((const unsigned int*)ei, Wg2, n);

    int eblk = (E + TILE_E - 1) / TILE_E;
    k_edge_all<<<eblk, 256>>>(ei, ex, W1, b1, W2, b2, E, n);

    k_scan1<<<nblk, SCAN_B>>>(n);
    k_scan2<<<1, SCAN_B>>>(nblk);
    k_scan3<<<nblk, SCAN_B>>>(n, E);

    k_permute<<<(E + 255) / 256, 256>>>(E);

    // join: gather1 needs both gemm1 (h1) and permute (CSR)
    cudaStreamWaitEvent(0, evJoin, 0);
    k_gather1<<<(n + GW - 1) / GW, 512>>>(bg1, n);

    k_gather2<<<(n * 32 + 255) / 256, 256>>>(out, bg2, n);
}

// round 17
// speedup vs baseline: 1.2224x; 1.0442x over previous
#include <cuda_runtime.h>
#include <cuda_fp16.h>
#include <mma.h>
#include <math.h>

using namespace nvcuda;

#define NMAX   50000
#define E_MAX  1600000
#define F_IN   128
#define F_HID  128
#define F_OUT  40
#define EF     16
#define EH     32
#define SCAN_B 256
#define TILE_E 512     // edges per CTA in edge kernel
#define EX_LD  24      // padded halfs per staged ex row
#define C_LD   36      // padded floats per staged c row
#define GW     16      // nodes (warps) per gather1 CTA
#define A_LD   136     // halfs per staged acc row
#define N_PAD  48      // Wg2 n padded to 48

// ---------------- scratch (static device globals; no allocs allowed) --------
__device__ int      g_is64;
__device__ unsigned g_pack[E_MAX];       // (row:16 | col:16), clamped
__device__ float    g_ew  [E_MAX];
__device__ float    g_deg [NMAX];
__device__ float    g_dinv[NMAX];
__device__ int      g_cnt [NMAX];
__device__ int      g_rowptr[NMAX + 1];
__device__ int      g_cursor[NMAX];
__device__ int      g_bsum[((NMAX + SCAN_B - 1) / SCAN_B) + 1];
__device__ unsigned g_srcw[E_MAX];       // (src:16 | fp16 weight:16)
__device__ __half   g_h1h [(size_t)NMAX * F_HID];
__device__ __half   g_h2h [(size_t)NMAX * F_OUT];
__device__ __half   g_wg2h[F_HID * N_PAD];

__device__ __forceinline__ float4 h4_to_f4(uint2 v) {
    __half2 h0 = *reinterpret_cast<__half2*>(&v.x);
    __half2 h1 = *reinterpret_cast<__half2*>(&v.y);
    float2 f0 = __half22float2(h0);
    float2 f1 = __half22float2(h1);
    return make_float4(f0.x, f0.y, f1.x, f1.y);
}
__device__ __forceinline__ uint2 f4_to_h4(float4 v) {
    __half2 a = __floats2half2_rn(v.x, v.y);
    __half2 b = __floats2half2_rn(v.z, v.w);
    uint2 r;
    r.x = *reinterpret_cast<unsigned int*>(&a);
    r.y = *reinterpret_cast<unsigned int*>(&b);
    return r;
}
__device__ __forceinline__ void unpack_sw(unsigned v, int& src, float& w) {
    src = (int)(v >> 16);
    unsigned short hbits = (unsigned short)(v & 0xffffu);
    w = __half2float(__ushort_as_half(hbits));
}

// ---------------- node init: cnt=0, deg=1; detect dtype; convert Wg2->fp16 --
__global__ void k_node_init(const unsigned int* __restrict__ p,
                            const float* __restrict__ Wg2, int n) {
    int i = blockIdx.x * blockDim.x + threadIdx.x;
    if (blockIdx.x == 0) {
        unsigned v = p[2 * threadIdx.x + 1];
        int any = __syncthreads_or(v != 0u);
        if (threadIdx.x == 0) g_is64 = any ? 0 : 1;
    }
    if (i < F_HID * N_PAD) {
        int k = i / N_PAD, nn = i % N_PAD;
        g_wg2h[i] = (nn < F_OUT) ? __float2half_rn(Wg2[k * F_OUT + nn])
                                 : __ushort_as_half((unsigned short)0);
    }
    if (i < n) { g_cnt[i] = 0; g_deg[i] = 1.0f; }
}

// ---------------- idx: convert+clamp+pack, histogram -------------------------
__global__ __launch_bounds__(256) void k_idx(const void* __restrict__ ei, int E, int n) {
    int e = blockIdx.x * blockDim.x + threadIdx.x;
    if (e >= E) return;
    int r, c;
    if (g_is64) { const long long* p = (const long long*)ei;
                  r = (int)p[e]; c = (int)p[E + e]; }
    else        { const int* p = (const int*)ei;
                  r = p[e]; c = p[E + e]; }
    r = r < 0 ? 0 : (r >= n ? n - 1 : r);
    c = c < 0 ? 0 : (c >= n ? n - 1 : c);
    g_pack[e] = ((unsigned)r << 16) | (unsigned)c;
    atomicAdd(&g_cnt[c], 1);
}

// ---------------- edge MLP (tensor-core): ew + deg ---------------------------
__global__ __launch_bounds__(256) void k_edge_mlp(
    const float* __restrict__ ex,
    const float* __restrict__ W1, const float* __restrict__ b1,
    const float* __restrict__ W2, const float* __restrict__ b2, int E)
{
    __shared__ __half s_exh[TILE_E * EX_LD];
    __shared__ __half s_w1h[16 * 32];
    __shared__ float  s_c[8][16 * C_LD];
    __shared__ float  s_b1[EH];
    __shared__ float  s_w2[EH];
    __shared__ float  s_b2;

    int tid = threadIdx.x;
    int e_base = blockIdx.x * TILE_E;

    {
        int i0 = tid * 2;
        s_w1h[i0]     = __float2half_rn(W1[i0]);
        s_w1h[i0 + 1] = __float2half_rn(W1[i0 + 1]);
    }
    if (tid < EH) { s_b1[tid] = b1[tid]; s_w2[tid] = W2[tid]; }
    if (tid == 0) s_b2 = b2[0];

    {
        const float4* ex4 = (const float4*)ex;
#pragma unroll
        for (int it = 0; it < 8; it++) {
            int f = tid + it * 256;
            int e_loc = f >> 2, q = f & 3;
            int e = e_base + e_loc;
            float4 v = (e < E) ? ex4[(size_t)e * 4 + q]
                               : make_float4(0.f, 0.f, 0.f, 0.f);
            __half2* dst = (__half2*)(s_exh + e_loc * EX_LD + q * 4);
            dst[0] = __floats2half2_rn(v.x, v.y);
            dst[1] = __floats2half2_rn(v.z, v.w);
        }
    }
    __syncthreads();

    int wid = tid >> 5, lane = tid & 31;
    wmma::fragment<wmma::matrix_b, 16, 16, 16, __half, wmma::row_major> bf0, bf1;
    wmma::load_matrix_sync(bf0, s_w1h,      32);
    wmma::load_matrix_sync(bf1, s_w1h + 16, 32);

    float* cbuf = s_c[wid];
    int row = lane & 15, hh = lane >> 4;
    const float* bb = s_b1 + hh * 16;
    const float* ww = s_w2 + hh * 16;

#pragma unroll
    for (int t4 = 0; t4 < 4; t4++) {
        int tile = wid * 4 + t4;
        wmma::fragment<wmma::matrix_a, 16, 16, 16, __half, wmma::row_major> af;
        wmma::load_matrix_sync(af, s_exh + tile * 16 * EX_LD, EX_LD);
        wmma::fragment<wmma::accumulator, 16, 16, 16, float> c0, c1;
        wmma::fill_fragment(c0, 0.f);
        wmma::fill_fragment(c1, 0.f);
        wmma::mma_sync(c0, af, bf0, c0);
        wmma::mma_sync(c1, af, bf1, c1);
        wmma::store_matrix_sync(cbuf,      c0, C_LD, wmma::mem_row_major);
        wmma::store_matrix_sync(cbuf + 16, c1, C_LD, wmma::mem_row_major);
        __syncwarp();

        int e = e_base + tile * 16 + row;
        const float* crow = cbuf + row * C_LD + hh * 16;
        float z = 0.f;
#pragma unroll
        for (int k = 0; k < 16; k++) {
            float a = crow[k] + bb[k];
            z = fmaf(fmaxf(a, 0.f), ww[k], z);
        }
        z += __shfl_xor_sync(0xffffffffu, z, 16);
        if (hh == 0 && e < E) {
            float w = 1.0f / (1.0f + __expf(-(z + s_b2)));
            g_ew[e] = w;
            atomicAdd(&g_deg[g_pack[e] & 0xffffu], w);
        }
        __syncwarp();
    }
}

// ---------------- dinv = rsqrt(deg) (after MLP) ------------------------------
__global__ void k_dinv(int n) {
    int i = blockIdx.x * blockDim.x + threadIdx.x;
    if (i < n) {
        float d = g_deg[i];
        g_dinv[i] = (d > 0.0f) ? rsqrtf(d) : 0.0f;
    }
}

// ---------------- scan pass 1 (side stream) ----------------------------------
__global__ __launch_bounds__(SCAN_B) void k_scan1(int n) {
    __shared__ int warp_sums[8];
    int tid = threadIdx.x, lane = tid & 31, wid = tid >> 5;
    int i = blockIdx.x * SCAN_B + tid;
    int v = (i < n) ? g_cnt[i] : 0;
    int incl = v;
#pragma unroll
    for (int o = 1; o < 32; o <<= 1) {
        int t = __shfl_up_sync(0xffffffffu, incl, o);
        if (lane >= o) incl += t;
    }
    if (lane == 31) warp_sums[wid] = incl;
    __syncthreads();
    if (wid == 0 && lane < 8) {
        int ws = warp_sums[lane];
#pragma unroll
        for (int o = 1; o < 8; o <<= 1) {
            int t = __shfl_up_sync(0xffu, ws, o);
            if (lane >= o) ws += t;
        }
        warp_sums[lane] = ws;
    }
    __syncthreads();
    int excl = incl - v + (wid > 0 ? warp_sums[wid - 1] : 0);
    if (i < n) g_rowptr[i] = excl;
    if (tid == SCAN_B - 1) g_bsum[blockIdx.x] = excl + v;
}

// ---------------- scan pass 2 (side stream) ----------------------------------
__global__ __launch_bounds__(SCAN_B) void k_scan2(int nblk) {
    __shared__ int s[SCAN_B];
    int tid = threadIdx.x;
    s[tid] = (tid < nblk) ? g_bsum[tid] : 0;
    __syncthreads();
    for (int o = 1; o < SCAN_B; o <<= 1) {
        int t = (tid >= o) ? s[tid - o] : 0;
        __syncthreads();
        s[tid] += t;
        __syncthreads();
    }
    if (tid < nblk) g_bsum[tid] = (tid > 0) ? s[tid - 1] : 0;
}

// ---------------- scan pass 3: offsets + cursor (side stream) ----------------
__global__ __launch_bounds__(SCAN_B) void k_scan3(int n, int E) {
    int i = blockIdx.x * SCAN_B + threadIdx.x;
    if (i < n) {
        int v = g_rowptr[i] + g_bsum[blockIdx.x];
        g_rowptr[i] = v;
        g_cursor[i] = v;
    }
    if (i == 0) g_rowptr[n] = E;
}

// ---------------- build CSR: scatter packed (src|w) into slot of dst --------
__global__ void k_permute(int E) {
    int e = blockIdx.x * blockDim.x + threadIdx.x;
    if (e >= E) return;
    unsigned pk = g_pack[e];
    int r = (int)(pk >> 16), c = (int)(pk & 0xffffu);
    float w = g_ew[e] * g_dinv[r] * g_dinv[c];
    int pos = atomicAdd(&g_cursor[c], 1);
    unsigned hw = (unsigned)__half_as_ushort(__float2half_rn(w));
    g_srcw[pos] = ((unsigned)r << 16) | hw;
}

// ---------------- h1 = x @ Wg1  -> fp16 --------------------------------------
#define G1_ROWS 32
__global__ __launch_bounds__(128) void k_gemm1(
    const float* __restrict__ x, const float* __restrict__ W, int n)
{
    __shared__ float4 xs[G1_ROWS * 32];
    int r0  = blockIdx.x * G1_ROWS;
    int tid = threadIdx.x;
    for (int i = tid; i < G1_ROWS * 32; i += 128) {
        int rr = i >> 5, kk = i & 31;
        int row = r0 + rr;
        xs[i] = (row < n) ? ((const float4*)x)[(size_t)row * 32 + kk]
                          : make_float4(0.f, 0.f, 0.f, 0.f);
    }
    __syncthreads();

    int j = tid;
    float acc[G1_ROWS];
#pragma unroll
    for (int r = 0; r < G1_ROWS; r++) acc[r] = 0.0f;

    for (int k4 = 0; k4 < 32; k4++) {
        float w0 = W[(k4*4+0) * F_HID + j];
        float w1 = W[(k4*4+1) * F_HID + j];
        float w2 = W[(k4*4+2) * F_HID + j];
        float w3 = W[(k4*4+3) * F_HID + j];
#pragma unroll
        for (int r = 0; r < G1_ROWS; r++) {
            float4 xv = xs[r * 32 + k4];
            acc[r] = fmaf(xv.x, w0, fmaf(xv.y, w1, fmaf(xv.z, w2, fmaf(xv.w, w3, acc[r]))));
        }
    }
#pragma unroll
    for (int r = 0; r < G1_ROWS; r++) {
        int row = r0 + r;
        if (row < n) g_h1h[(size_t)row * F_HID + j] = __float2half_rn(acc[r]);
    }
}

// ---------------- conv1 gather FUSED with gemm2 ------------------------------
__global__ __launch_bounds__(512) void k_gather1(const float* __restrict__ bg1, int n)
{
    __shared__ __align__(32) __half s_a[GW * A_LD];
    __shared__ __align__(32) __half s_w[F_HID * N_PAD];
    __shared__ __align__(32) float  s_d[16 * N_PAD];

    int tid = threadIdx.x, wid = tid >> 5, lane = tid & 31;

    {
        const unsigned* src = (const unsigned*)g_wg2h;
        unsigned* dst = (unsigned*)s_w;
#pragma unroll
        for (int i = 0; i < (F_HID * N_PAD / 2) / 512; i++)
            dst[tid + i * 512] = src[tid + i * 512];
    }

    int c = blockIdx.x * GW + wid;
    float4 acc = make_float4(0.f, 0.f, 0.f, 0.f);
    if (c < n) {
        float di = g_dinv[c];
        float sl = di * di;
        acc = ((const float4*)bg1)[lane];
        {
            const uint2* rp = (const uint2*)(g_h1h + (size_t)c * F_HID);
            float4 hv = h4_to_f4(rp[lane]);
            acc.x = fmaf(sl, hv.x, acc.x);
            acc.y = fmaf(sl, hv.y, acc.y);
            acc.z = fmaf(sl, hv.z, acc.z);
            acc.w = fmaf(sl, hv.w, acc.w);
        }
        int beg = g_rowptr[c], end = g_rowptr[c + 1];
        float4 a2 = make_float4(0.f, 0.f, 0.f, 0.f);
        int j = beg;
        for (; j + 1 < end; j += 2) {
            unsigned m0 = g_srcw[j];
            unsigned m1 = g_srcw[j + 1];
            int s0, s1; float w0, w1;
            unpack_sw(m0, s0, w0);
            unpack_sw(m1, s1, w1);
            float4 v0 = h4_to_f4(((const uint2*)(g_h1h + (size_t)s0 * F_HID))[lane]);
            float4 v1 = h4_to_f4(((const uint2*)(g_h1h + (size_t)s1 * F_HID))[lane]);
            acc.x = fmaf(w0, v0.x, acc.x);  a2.x = fmaf(w1, v1.x, a2.x);
            acc.y = fmaf(w0, v0.y, acc.y);  a2.y = fmaf(w1, v1.y, a2.y);
            acc.z = fmaf(w0, v0.z, acc.z);  a2.z = fmaf(w1, v1.z, a2.z);
            acc.w = fmaf(w0, v0.w, acc.w);  a2.w = fmaf(w1, v1.w, a2.w);
        }
        if (j < end) {
            int s0; float w0;
            unpack_sw(g_srcw[j], s0, w0);
            float4 v0 = h4_to_f4(((const uint2*)(g_h1h + (size_t)s0 * F_HID))[lane]);
            acc.x = fmaf(w0, v0.x, acc.x);
            acc.y = fmaf(w0, v0.y, acc.y);
            acc.z = fmaf(w0, v0.z, acc.z);
            acc.w = fmaf(w0, v0.w, acc.w);
        }
        acc.x = fmaxf(acc.x + a2.x, 0.f);
        acc.y = fmaxf(acc.y + a2.y, 0.f);
        acc.z = fmaxf(acc.z + a2.z, 0.f);
        acc.w = fmaxf(acc.w + a2.w, 0.f);
    }
    ((uint2*)(s_a + wid * A_LD))[lane] = f4_to_h4(acc);
    __syncthreads();

    if (wid < 3) {
        wmma::fragment<wmma::accumulator, 16, 16, 16, float> cf;
        wmma::fill_fragment(cf, 0.f);
#pragma unroll
        for (int k = 0; k < 8; k++) {
            wmma::fragment<wmma::matrix_a, 16, 16, 16, __half, wmma::row_major> af;
            wmma::fragment<wmma::matrix_b, 16, 16, 16, __half, wmma::row_major> bf;
            wmma::load_matrix_sync(af, s_a + k * 16, A_LD);
            wmma::load_matrix_sync(bf, s_w + k * 16 * N_PAD + wid * 16, N_PAD);
            wmma::mma_sync(cf, af, bf, cf);
        }
        wmma::store_matrix_sync(s_d + wid * 16, cf, N_PAD, wmma::mem_row_major);
    }
    __syncthreads();

    for (int i = tid; i < GW * F_OUT; i += 512) {
        int r = i / F_OUT, col = i % F_OUT;
        int node = blockIdx.x * GW + r;
        if (node < n)
            g_h2h[(size_t)node * F_OUT + col] = __float2half_rn(s_d[r * N_PAD + col]);
    }
}

// ---------------- conv2 gather -----------------------------------------------
__global__ __launch_bounds__(256) void k_gather2(float* __restrict__ out,
                                                 const float* __restrict__ bg2, int n)
{
    int c    = (blockIdx.x * blockDim.x + threadIdx.x) >> 5;
    int lane = threadIdx.x & 31;
    if (c >= n || lane >= 20) return;
    float di = g_dinv[c];
    float sl = di * di;

    float2 acc = ((const float2*)bg2)[lane];
    {
        const __half2* rp = (const __half2*)(g_h2h + (size_t)c * F_OUT);
        float2 hv = __half22float2(rp[lane]);
        acc.x = fmaf(sl, hv.x, acc.x);
        acc.y = fmaf(sl, hv.y, acc.y);
    }
    float2 a2 = make_float2(0.f, 0.f);

    int beg = g_rowptr[c], end = g_rowptr[c + 1];
    int j = beg;
    for (; j + 1 < end; j += 2) {
        int s0, s1; float w0, w1;
        unpack_sw(g_srcw[j], s0, w0);
        unpack_sw(g_srcw[j + 1], s1, w1);
        const __half2* p0 = (const __half2*)(g_h2h + (size_t)s0 * F_OUT);
        const __half2* p1 = (const __half2*)(g_h2h + (size_t)s1 * F_OUT);
        float2 v0 = __half22float2(p0[lane]);
        float2 v1 = __half22float2(p1[lane]);
        acc.x = fmaf(w0, v0.x, acc.x);  a2.x = fmaf(w1, v1.x, a2.x);
        acc.y = fmaf(w0, v0.y, acc.y);  a2.y = fmaf(w1, v1.y, a2.y);
    }
    if (j < end) {
        int s0; float w0;
        unpack_sw(g_srcw[j], s0, w0);
        const __half2* p0 = (const __half2*)(g_h2h + (size_t)s0 * F_OUT);
        float2 v0 = __half22float2(p0[lane]);
        acc.x = fmaf(w0, v0.x, acc.x);
        acc.y = fmaf(w0, v0.y, acc.y);
    }
    acc.x += a2.x;
    acc.y += a2.y;
    ((float2*)(out + (size_t)c * F_OUT))[lane] = acc;
}

// ---------------- launch -----------------------------------------------------
extern "C" void kernel_launch(void* const* d_in, const int* in_sizes, int n_in,
                              void* d_out, int out_size)
{
    const float* x   = (const float*)d_in[0];
    const void*  ei  = d_in[1];
    const float* ex  = (const float*)d_in[2];
    const float* W1  = (const float*)d_in[3];
    const float* b1  = (const float*)d_in[4];
    const float* W2  = (const float*)d_in[5];
    const float* b2  = (const float*)d_in[6];
    const float* Wg1 = (const float*)d_in[7];
    const float* bg1 = (const float*)d_in[8];
    const float* Wg2 = (const float*)d_in[9];
    const float* bg2 = (const float*)d_in[10];
    float* out = (float*)d_out;

    int n = in_sizes[0] / F_IN;       // 50000
    int E = in_sizes[2] / EF;         // 1600000
    int nblk = (n + SCAN_B - 1) / SCAN_B;

    static cudaStream_t s2 = nullptr, s3 = nullptr;
    static cudaEvent_t  evFork = nullptr, evJoin = nullptr, evIdx = nullptr, evScan = nullptr;
    if (s2 == nullptr) {
        cudaStreamCreateWithFlags(&s2, cudaStreamNonBlocking);
        cudaStreamCreateWithFlags(&s3, cudaStreamNonBlocking);
        cudaEventCreateWithFlags(&evFork, cudaEventDisableTiming);
        cudaEventCreateWithFlags(&evJoin, cudaEventDisableTiming);
        cudaEventCreateWithFlags(&evIdx,  cudaEventDisableTiming);
        cudaEventCreateWithFlags(&evScan, cudaEventDisableTiming);
    }

    // fork 1: gemm1 depends only on x,Wg1 — side stream s2
    cudaEventRecord(evFork, 0);
    cudaStreamWaitEvent(s2, evFork, 0);
    k_gemm1<<<(n + G1_ROWS - 1) / G1_ROWS, 128, 0, s2>>>(x, Wg1, n);
    cudaEventRecord(evJoin, s2);

    // main: node init + index/histogram pass
    k_node_init<<<(n + 255) / 256, 256>>>((const unsigned int*)ei, Wg2, n);
    k_idx<<<(E + 255) / 256, 256>>>(ei, E, n);
    cudaEventRecord(evIdx, 0);

    // fork 2: scan chain on s3, concurrent with edge MLP on main
    cudaStreamWaitEvent(s3, evIdx, 0);
    k_scan1<<<nblk, SCAN_B, 0, s3>>>(n);
    k_scan2<<<1, SCAN_B, 0, s3>>>(nblk);
    k_scan3<<<nblk, SCAN_B, 0, s3>>>(n, E);
    cudaEventRecord(evScan, s3);

    // main: edge MLP (needs g_pack for deg), then dinv
    int eblk = (E + TILE_E - 1) / TILE_E;
    k_edge_mlp<<<eblk, 256>>>(ex, W1, b1, W2, b2, E);
    k_dinv<<<(n + 255) / 256, 256>>>(n);

    // join scan chain, then permute
    cudaStreamWaitEvent(0, evScan, 0);
    k_permute<<<(E + 255) / 256, 256>>>(E);

    // join gemm1, then fused gather1+gemm2, then gather2
    cudaStreamWaitEvent(0, evJoin, 0);
    k_gather1<<<(n + GW - 1) / GW, 512>>>(bg1, n);

    k_gather2<<<(n * 32 + 255) / 256, 256>>>(out, bg2, n);
}